// round 16
// baseline (speedup 1.0000x reference)
#include <cuda_runtime.h>
#include <math.h>

// GeodesicLoss: reference initializes velocity to zero, so the geodesic ODE
// acc = -Gamma v v is identically zero for all 10 steps -> traj == outputs.
// Result is exactly mean_b || outputs_b - targets_b ||_2.
// Pure streaming reduction over 128 MiB -> DRAM-bound.
//
// R16: middle point of the measured tradeoff: 8192 blocks x 256 threads,
// ITERS=2 -> 4 front-batched LDG.128 per thread. 4 float4 destinations
// (16 regs) fit FULLY live inside ptxas's chosen regs=40 allocation
// (8-load batches at 4096 blocks only realized ~4-5 of 8), while 2x the
// block count supplies warp-level MLP like the one-shot 72%-DRAM shape.
// Tail = R3 protocol (fence + returning atomicAdd, winner reduces 2048
// float4 in fixed order -> deterministic; counter self-resets).

#define B_ROWS   524288
#define D_DIM    32
#define THREADS  256
#define NBLOCKS  8192
#define ROWS_PER_ITER (THREADS / 8)                         // 32 rows / block-iter
#define ITERS 2                                             // 64 rows / block
// sanity: NBLOCKS * ROWS_PER_ITER * ITERS == B_ROWS
#define F4_PER_ITER (ROWS_PER_ITER * (D_DIM / 4))           // 256 float4 stride

__device__ float        g_partials[NBLOCKS];
__device__ unsigned int g_done_count = 0;

__global__ __launch_bounds__(THREADS, 4)
void geodesic_loss_fused_kernel(const float* __restrict__ outputs,
                                const float* __restrict__ targets,
                                float* __restrict__ out) {
    const int sub      = threadIdx.x & 7;          // which float4 of the row
    const int row_in_b = threadIdx.x >> 3;         // row slot within block-iter
    const int base_row = blockIdx.x * (ROWS_PER_ITER * ITERS);

    const float4* __restrict__ o4 = reinterpret_cast<const float4*>(outputs);
    const float4* __restrict__ t4 = reinterpret_cast<const float4*>(targets);

    const int idx0 = (base_row + row_in_b) * (D_DIM / 4) + sub;

    // ---- front-batched loads: 4 independent LDG.128, all live in regs ----
    float4 a0 = o4[idx0 + 0 * F4_PER_ITER];
    float4 a1 = o4[idx0 + 1 * F4_PER_ITER];
    float4 b0 = t4[idx0 + 0 * F4_PER_ITER];
    float4 b1 = t4[idx0 + 1 * F4_PER_ITER];

    float dx, dy, dz, dw;
    #define SSQ(a, b) (dx = a.x - b.x, dy = a.y - b.y, dz = a.z - b.z, \
                       dw = a.w - b.w, dx*dx + dy*dy + dz*dz + dw*dw)
    float s0 = SSQ(a0, b0);
    float s1 = SSQ(a1, b1);
    #undef SSQ

    // Reduce the 8 lanes covering each row (2 independent chains)
    s0 += __shfl_xor_sync(0xFFFFFFFFu, s0, 1);
    s1 += __shfl_xor_sync(0xFFFFFFFFu, s1, 1);
    s0 += __shfl_xor_sync(0xFFFFFFFFu, s0, 2);
    s1 += __shfl_xor_sync(0xFFFFFFFFu, s1, 2);
    s0 += __shfl_xor_sync(0xFFFFFFFFu, s0, 4);
    s1 += __shfl_xor_sync(0xFFFFFFFFu, s1, 4);

    float acc = 0.0f;
    if (sub == 0)
        acc = sqrtf(s0) + sqrtf(s1);

    // Combine the 4 row-accumulators per warp (lanes 0,8,16,24 nonzero)
    acc += __shfl_xor_sync(0xFFFFFFFFu, acc, 8);
    acc += __shfl_xor_sync(0xFFFFFFFFu, acc, 16);

    __shared__ float wsum[THREADS / 32];
    if ((threadIdx.x & 31) == 0)
        wsum[threadIdx.x >> 5] = acc;
    __syncthreads();

    __shared__ bool s_is_last;
    if (threadIdx.x == 0) {
        float bsum = 0.0f;
        #pragma unroll
        for (int i = 0; i < THREADS / 32; i++)
            bsum += wsum[i];
        g_partials[blockIdx.x] = bsum;
        __threadfence();
        unsigned int prev = atomicAdd(&g_done_count, 1u);
        s_is_last = (prev == NBLOCKS - 1);
    }
    __syncthreads();

    if (s_is_last) {
        // Final reduce over NBLOCKS partials via float4, fixed order.
        const float4* __restrict__ p4 =
            reinterpret_cast<const float4*>(g_partials);
        float s = 0.0f;
        #pragma unroll
        for (int i = threadIdx.x; i < NBLOCKS / 4; i += THREADS) {
            float4 v = p4[i];
            s += (v.x + v.y) + (v.z + v.w);
        }

        s += __shfl_xor_sync(0xFFFFFFFFu, s, 1);
        s += __shfl_xor_sync(0xFFFFFFFFu, s, 2);
        s += __shfl_xor_sync(0xFFFFFFFFu, s, 4);
        s += __shfl_xor_sync(0xFFFFFFFFu, s, 8);
        s += __shfl_xor_sync(0xFFFFFFFFu, s, 16);

        __shared__ float fsum[THREADS / 32];
        if ((threadIdx.x & 31) == 0)
            fsum[threadIdx.x >> 5] = s;
        __syncthreads();

        if (threadIdx.x == 0) {
            float tot = 0.0f;
            #pragma unroll
            for (int i = 0; i < THREADS / 32; i++)
                tot += fsum[i];
            out[0] = tot * (1.0f / (float)B_ROWS);
            g_done_count = 0;   // reset for next graph replay
        }
    }
}

extern "C" void kernel_launch(void* const* d_in, const int* in_sizes, int n_in,
                              void* d_out, int out_size) {
    const float* outputs = (const float*)d_in[0];
    const float* targets = (const float*)d_in[1];
    // d_in[2] (christoffel_symbols) is mathematically dead: vel starts at 0.
    float* out = (float*)d_out;

    geodesic_loss_fused_kernel<<<NBLOCKS, THREADS>>>(outputs, targets, out);
}

// round 17
// speedup vs baseline: 1.0056x; 1.0056x over previous
#include <cuda_runtime.h>
#include <math.h>
#include <stdint.h>

// GeodesicLoss: reference initializes velocity to zero, so the geodesic ODE
// acc = -Gamma v v is identically zero for all 10 steps -> traj == outputs.
// Result is exactly mean_b || outputs_b - targets_b ||_2.
// Pure streaming reduction over 128 MiB -> DRAM-bound.
//
// R17: replace the register-capped LDG stream (plateaued at 62-72% DRAM,
// in-flight bytes limited by regs=40) with a TMA (cp.async.bulk) double-
// buffered pipeline: 2 stages x (8KB o + 8KB t) in SMEM per block ->
// ~224KB/SM in flight, far above the ~15KB/SM latency-BW product needed to
// saturate HBM. Compute = conflict-free LDS float4 + 8-lane shuffle reduce.
// Tail = champion R3 protocol (fence + atomicAdd, fixed-order winner reduce
// over 2048 partials -> deterministic; counter self-resets for replay).

#define B_ROWS   524288
#define D_DIM    32
#define THREADS  256
#define NBLOCKS  2048
#define ROWS_PER_BLOCK 256                    // NBLOCKS*256 = B_ROWS
#define TILE_ROWS 64
#define NTILES    (ROWS_PER_BLOCK / TILE_ROWS)   // 4
#define TILE_F4   (TILE_ROWS * (D_DIM / 4))      // 512 float4 = 8KB
#define TILE_BYTES (TILE_F4 * 16)                // 8192
#define TILE_FLOATS (TILE_ROWS * D_DIM)          // 2048

__device__ float        g_partials[NBLOCKS];
__device__ unsigned int g_done_count = 0;

__device__ __forceinline__ uint32_t smem_u32(const void* p) {
    uint32_t a;
    asm("{ .reg .u64 t; cvta.to.shared.u64 t, %1; cvt.u32.u64 %0, t; }"
        : "=r"(a) : "l"(p));
    return a;
}

__device__ __forceinline__ void mbar_init(uint32_t mbar, uint32_t count) {
    asm volatile("mbarrier.init.shared.b64 [%0], %1;"
                 :: "r"(mbar), "r"(count) : "memory");
}

__device__ __forceinline__ void mbar_expect_tx(uint32_t mbar, uint32_t bytes) {
    asm volatile("mbarrier.arrive.expect_tx.shared.b64 _, [%0], %1;"
                 :: "r"(mbar), "r"(bytes) : "memory");
}

__device__ __forceinline__ void bulk_g2s(uint32_t dst_smem, const void* src,
                                         uint32_t bytes, uint32_t mbar) {
    asm volatile(
        "cp.async.bulk.shared::cluster.global.mbarrier::complete_tx::bytes "
        "[%0], [%1], %2, [%3];"
        :: "r"(dst_smem), "l"(src), "r"(bytes), "r"(mbar) : "memory");
}

__device__ __forceinline__ void mbar_wait(uint32_t mbar, uint32_t parity) {
    asm volatile(
        "{\n\t"
        ".reg .pred P;\n\t"
        "WAIT_%=:\n\t"
        "mbarrier.try_wait.parity.acquire.cta.shared::cta.b64 P, [%0], %1, 0x989680;\n\t"
        "@P bra.uni DONE_%=;\n\t"
        "bra.uni WAIT_%=;\n\t"
        "DONE_%=:\n\t"
        "}"
        :: "r"(mbar), "r"(parity) : "memory");
}

__global__ __launch_bounds__(THREADS)
void geodesic_loss_tma_kernel(const float* __restrict__ outputs,
                              const float* __restrict__ targets,
                              float* __restrict__ out) {
    __shared__ alignas(128) float4 s_o[2][TILE_F4];   // 2 x 8KB
    __shared__ alignas(128) float4 s_t[2][TILE_F4];   // 2 x 8KB
    __shared__ alignas(8) unsigned long long s_mbar[2];
    __shared__ float wsum[THREADS / 32];
    __shared__ bool s_is_last;

    const int tid = threadIdx.x;
    const int sub = tid & 7;                 // which float4 of the row
    const int rsl = tid >> 3;                // row slot (0..31) per pass

    const uint32_t mb0 = smem_u32(&s_mbar[0]);
    const uint32_t mb1 = smem_u32(&s_mbar[1]);

    if (tid == 0) {
        mbar_init(mb0, 1);
        mbar_init(mb1, 1);
        asm volatile("fence.proxy.async.shared::cta;" ::: "memory");
    }
    __syncthreads();

    const float* o_base = outputs + (size_t)blockIdx.x * (ROWS_PER_BLOCK * D_DIM);
    const float* t_base = targets + (size_t)blockIdx.x * (ROWS_PER_BLOCK * D_DIM);

    // Prologue: fill both stages.
    if (tid == 0) {
        mbar_expect_tx(mb0, 2 * TILE_BYTES);
        bulk_g2s(smem_u32(&s_o[0][0]), o_base + 0 * TILE_FLOATS, TILE_BYTES, mb0);
        bulk_g2s(smem_u32(&s_t[0][0]), t_base + 0 * TILE_FLOATS, TILE_BYTES, mb0);
        mbar_expect_tx(mb1, 2 * TILE_BYTES);
        bulk_g2s(smem_u32(&s_o[1][0]), o_base + 1 * TILE_FLOATS, TILE_BYTES, mb1);
        bulk_g2s(smem_u32(&s_t[1][0]), t_base + 1 * TILE_FLOATS, TILE_BYTES, mb1);
    }

    float acc = 0.0f;

    #pragma unroll
    for (int it = 0; it < NTILES; it++) {
        const int b = it & 1;
        const uint32_t mb = b ? mb1 : mb0;
        mbar_wait(mb, (it >> 1) & 1);

        // 64 rows per tile, 2 passes of 32 rows (8 lanes per row).
        #pragma unroll
        for (int p = 0; p < 2; p++) {
            const int r = p * 32 + rsl;
            float4 a = s_o[b][r * 8 + sub];
            float4 c = s_t[b][r * 8 + sub];
            float dx = a.x - c.x;
            float dy = a.y - c.y;
            float dz = a.z - c.z;
            float dw = a.w - c.w;
            float s = dx * dx + dy * dy + dz * dz + dw * dw;
            s += __shfl_xor_sync(0xFFFFFFFFu, s, 1);
            s += __shfl_xor_sync(0xFFFFFFFFu, s, 2);
            s += __shfl_xor_sync(0xFFFFFFFFu, s, 4);
            if (sub == 0)
                acc += sqrtf(s);
        }

        __syncthreads();   // whole block done reading buffer b

        if (it + 2 < NTILES && tid == 0) {
            const int nt = it + 2;
            mbar_expect_tx(mb, 2 * TILE_BYTES);
            bulk_g2s(smem_u32(&s_o[b][0]), o_base + nt * TILE_FLOATS, TILE_BYTES, mb);
            bulk_g2s(smem_u32(&s_t[b][0]), t_base + nt * TILE_FLOATS, TILE_BYTES, mb);
        }
    }

    // Combine the 4 per-row accumulators in this warp (lanes 0,8,16,24)
    acc += __shfl_xor_sync(0xFFFFFFFFu, acc, 8);
    acc += __shfl_xor_sync(0xFFFFFFFFu, acc, 16);

    if ((tid & 31) == 0)
        wsum[tid >> 5] = acc;
    __syncthreads();

    if (tid == 0) {
        float bsum = 0.0f;
        #pragma unroll
        for (int i = 0; i < THREADS / 32; i++)
            bsum += wsum[i];
        g_partials[blockIdx.x] = bsum;
        __threadfence();
        unsigned int prev = atomicAdd(&g_done_count, 1u);
        s_is_last = (prev == NBLOCKS - 1);
    }
    __syncthreads();

    if (s_is_last) {
        // Final reduce over 2048 partials (512 float4), fixed order.
        const float4* __restrict__ p4 =
            reinterpret_cast<const float4*>(g_partials);
        float s = 0.0f;
        #pragma unroll
        for (int i = tid; i < NBLOCKS / 4; i += THREADS) {
            float4 v = p4[i];
            s += (v.x + v.y) + (v.z + v.w);
        }

        s += __shfl_xor_sync(0xFFFFFFFFu, s, 1);
        s += __shfl_xor_sync(0xFFFFFFFFu, s, 2);
        s += __shfl_xor_sync(0xFFFFFFFFu, s, 4);
        s += __shfl_xor_sync(0xFFFFFFFFu, s, 8);
        s += __shfl_xor_sync(0xFFFFFFFFu, s, 16);

        __shared__ float fsum[THREADS / 32];
        if ((tid & 31) == 0)
            fsum[tid >> 5] = s;
        __syncthreads();

        if (tid == 0) {
            float tot = 0.0f;
            #pragma unroll
            for (int i = 0; i < THREADS / 32; i++)
                tot += fsum[i];
            out[0] = tot * (1.0f / (float)B_ROWS);
            g_done_count = 0;   // reset for next graph replay
        }
    }
}

extern "C" void kernel_launch(void* const* d_in, const int* in_sizes, int n_in,
                              void* d_out, int out_size) {
    const float* outputs = (const float*)d_in[0];
    const float* targets = (const float*)d_in[1];
    // d_in[2] (christoffel_symbols) is mathematically dead: vel starts at 0.
    float* out = (float*)d_out;

    geodesic_loss_tma_kernel<<<NBLOCKS, THREADS>>>(outputs, targets, out);
}